// round 14
// baseline (speedup 1.0000x reference)
#include <cuda_runtime.h>
#include <cstdint>
#include <cstddef>

// Problem constants
#define NN   50000
#define EE   800000
#define DD   128
#define HH   8

#define KC     64    // weight K-chunk staged in SMEM
#define NBUF   3     // weight ring slots

// edge kernel geometry
#define TILE_E 128
#define NTE    512
#define ASTE   132   // SMEM activation stride for 128-row tiles

// prep/node kernel geometry
#define NTP    256
#define ASTP   68

// ---------------- scratch (device globals: no allocation allowed) ----------
__device__ float g_msg[(size_t)EE * DD];      // 409.6 MB
__device__ float g_a[(size_t)EE * HH];        // 25.6 MB
__device__ float g_alpha[EE];                 // 3.2 MB
__device__ float g_agg[(size_t)NN * DD];      // 25.6 MB
__device__ float g_T[(size_t)NN * DD];        // nf @ W_node
__device__ float g_P[(size_t)NN * DD];        // nf[:, :64] @ aW1[0:64]
__device__ float g_Q[(size_t)NN * DD];        // nf[:, :64] @ aW1[64:128]
__device__ float g_max[HH];
__device__ float g_sum[HH];

// ---------------- helpers ---------------------------------------------------
__device__ __forceinline__ unsigned long long pack2(float x, float y) {
    unsigned long long r;
    asm("mov.b64 %0, {%1, %2};" : "=l"(r) : "f"(x), "f"(y));
    return r;
}
__device__ __forceinline__ float2 unpack2(unsigned long long v) {
    float2 f;
    asm("mov.b64 {%0, %1}, %2;" : "=f"(f.x), "=f"(f.y) : "l"(v));
    return f;
}
__device__ __forceinline__ void ffma2(unsigned long long& d,
                                      unsigned long long a,
                                      unsigned long long b) {
    asm("fma.rn.f32x2 %0, %1, %2, %0;" : "+l"(d) : "l"(a), "l"(b));
}
__device__ __forceinline__ float silu_f(float x) {
    return x / (1.0f + __expf(-x));
}
__device__ __forceinline__ void atomicMaxFloat(float* addr, float v) {
    if (v >= 0.0f) atomicMax((int*)addr, __float_as_int(v));
    else           atomicMin((unsigned int*)addr, __float_as_uint(v));
}

// ---------------- async copy -------------------------------------------------
__device__ __forceinline__ void cp_async16(void* sdst, const void* gsrc) {
    uint32_t s = (uint32_t)__cvta_generic_to_shared(sdst);
    asm volatile("cp.async.cg.shared.global [%0], [%1], 16;" :: "r"(s), "l"(gsrc));
}
#define CP_COMMIT() asm volatile("cp.async.commit_group;" ::: "memory")
#define CP_WAIT(n)  asm volatile("cp.async.wait_group %0;" :: "n"(n) : "memory")

template<int NT>
__device__ __forceinline__ void prefetch_chunk(const float* __restrict__ W,
                                               int rows, float* __restrict__ dst,
                                               int tid) {
    const float4* s = (const float4*)W;
    float4* d = (float4*)dst;
    int n = rows * 32;
    for (int i = tid; i < n; i += NT) cp_async16(d + i, s + i);
    CP_COMMIT();
}

// ---------------- GEMM core -------------------------------------------------
// C[ROWS x 128] += A_s[K][AS] (smem, transposed) * Wg[K][128].
// Column-strided lane mapping: lane colg owns columns {colg+32c, c=0..3}.
// Weights stream through a 3-slot cp.async ring; chunk0 of this stage must
// already be in slot pb; during the last chunk the first chunk of the next
// stage is prefetched.
template<int NT, int AS>
__device__ __forceinline__ void gemm_stage(const float* __restrict__ Wg, int K,
                                           const float* __restrict__ As,
                                           float* __restrict__ WsBase,
                                           unsigned long long (&acc)[4][4],
                                           int tid, bool zinit, int& pb,
                                           const float* __restrict__ nxtW,
                                           int nxtRows) {
    const int colg = tid & 31;
    const int rowb = (tid >> 5) * 8;
    if (zinit) {
#pragma unroll
        for (int rp = 0; rp < 4; rp++)
#pragma unroll
            for (int c = 0; c < 4; c++) acc[rp][c] = 0ull;
    }
    const int nc = (K + KC - 1) / KC;
    for (int c = 0; c < nc; c++) {
        if (c + 1 < nc) {
            int k0n = (c + 1) * KC;
            int rn = K - k0n; if (rn > KC) rn = KC;
            prefetch_chunk<NT>(Wg + (size_t)k0n * 128, rn,
                               WsBase + ((pb + 1) % NBUF) * (KC * 128), tid);
            CP_WAIT(1);
        } else if (nxtW) {
            int rn = nxtRows > KC ? KC : nxtRows;
            prefetch_chunk<NT>(nxtW, rn,
                               WsBase + ((pb + 1) % NBUF) * (KC * 128), tid);
            CP_WAIT(1);
        } else {
            CP_WAIT(0);
        }
        __syncthreads();
        const float* Ws = WsBase + pb * (KC * 128);
        int k0 = c * KC;
        int kc = K - k0; if (kc > KC) kc = KC;
#pragma unroll 4
        for (int k = 0; k < kc; k++) {
            const float* Ak = As + (k0 + k) * AS + rowb;
            ulonglong2 a01 = *(const ulonglong2*)(Ak);
            ulonglong2 a23 = *(const ulonglong2*)(Ak + 4);
            const float* Wk = Ws + k * 128 + colg;
            unsigned long long w2[4];
#pragma unroll
            for (int cc = 0; cc < 4; cc++) {
                float w = Wk[32 * cc];
                w2[cc] = pack2(w, w);
            }
#pragma unroll
            for (int cc = 0; cc < 4; cc++) {
                ffma2(acc[0][cc], a01.x, w2[cc]);
                ffma2(acc[1][cc], a01.y, w2[cc]);
                ffma2(acc[2][cc], a23.x, w2[cc]);
                ffma2(acc[3][cc], a23.y, w2[cc]);
            }
        }
        pb = (pb + 1) % NBUF;
    }
}

// epilogue: silu(acc + bias) written transposed to an activation buffer.
// Lane writes columns colg+32c -> STS lane stride 132 words == 4 mod 32
// (4-way conflict instead of 16-way).
template<int AS>
__device__ __forceinline__ void store_act(unsigned long long (&acc)[4][4],
                                          float* __restrict__ AsOut,
                                          const float* __restrict__ bias,
                                          int tid) {
    const int colg = tid & 31;
    const int rowb = (tid >> 5) * 8;
    float bb[4];
#pragma unroll
    for (int c = 0; c < 4; c++) bb[c] = bias[colg + 32 * c];
#pragma unroll
    for (int rp = 0; rp < 4; rp++)
#pragma unroll
        for (int c = 0; c < 4; c++) {
            float2 v = unpack2(acc[rp][c]);
            v.x = silu_f(v.x + bb[c]);
            v.y = silu_f(v.y + bb[c]);
            *(float2*)(AsOut + (colg + 32 * c) * AS + rowb + 2 * rp) = v;
        }
}

// plain store of acc to global [row][128] (4 coalesced 128B segments per row)
__device__ __forceinline__ void store_global(unsigned long long (&acc)[4][4],
                                             float* __restrict__ G,
                                             long r0base, int nv, int tid) {
    const int colg = tid & 31;
    const int rowb = (tid >> 5) * 8;
#pragma unroll
    for (int rp = 0; rp < 4; rp++) {
        float2 v[4];
#pragma unroll
        for (int c = 0; c < 4; c++) v[c] = unpack2(acc[rp][c]);
        int r0 = rowb + 2 * rp;
        if (r0 < nv) {
            float* g0 = G + (size_t)(r0base + r0) * 128 + colg;
#pragma unroll
            for (int c = 0; c < 4; c++) g0[32 * c] = v[c].x;
        }
        if (r0 + 1 < nv) {
            float* g1 = G + (size_t)(r0base + r0 + 1) * 128 + colg;
#pragma unroll
            for (int c = 0; c < 4; c++) g1[32 * c] = v[c].y;
        }
    }
}

// ---------------- init scratch -----------------------------------------------
__global__ void zero_agg() {
    int i = blockIdx.x * 256 + threadIdx.x;
    if (i < NN * DD) g_agg[i] = 0.0f;
}
__global__ void zero_heads() {
    int i = threadIdx.x;
    if (i < HH) { g_max[i] = -3.4e38f; g_sum[i] = 0.0f; }
}

// ---------------- per-node precompute ----------------------------------------
// T = nf @ W_node ; P = nf[:, :64] @ aW1[0:64] ; Q = nf[:, :64] @ aW1[64:128]
__global__ void __launch_bounds__(NTP, 1)
prep_kernel(const float* __restrict__ nf, const float* __restrict__ W_node,
            const float* __restrict__ aW1) {
    extern __shared__ float sm[];
    float* nfT = sm;                  // [128][ASTP]
    float* Ws  = sm + 128 * ASTP;     // [NBUF][KC][128]
    const int tid = threadIdx.x;
    const long n0 = (long)blockIdx.x * 64;
    int nv = (int)(NN - n0); if (nv > 64) nv = 64;

    int pb = 0;
    prefetch_chunk<NTP>(W_node, KC, Ws, tid);

    for (int i = tid; i < 64 * 128; i += NTP) {
        int r = i >> 7, d = i & 127;
        nfT[d * ASTP + r] = (r < nv) ? nf[(size_t)(n0 + r) * 128 + d] : 0.0f;
    }

    unsigned long long acc[4][4];
    gemm_stage<NTP, ASTP>(W_node, 128, nfT, Ws, acc, tid, true, pb, aW1, 64);
    store_global(acc, g_T, n0, nv, tid);
    gemm_stage<NTP, ASTP>(aW1, 64, nfT, Ws, acc, tid, true, pb, aW1 + 64 * 128, 64);
    store_global(acc, g_P, n0, nv, tid);
    gemm_stage<NTP, ASTP>(aW1 + 64 * 128, 64, nfT, Ws, acc, tid, true, pb, nullptr, 0);
    store_global(acc, g_Q, n0, nv, tid);
}

// ---------------- per-edge fused pipeline -------------------------------------
__global__ void __launch_bounds__(NTE, 1)
edge_kernel(const float* __restrict__ ea,   const float* __restrict__ esh,
            const float* __restrict__ fc1,  const float* __restrict__ b1,
            const float* __restrict__ fc2,  const float* __restrict__ b2,
            const float* __restrict__ fc3,  const float* __restrict__ b3,
            const float* __restrict__ W_sh, const float* __restrict__ aW1,
            const float* __restrict__ ab1,  const float* __restrict__ aW2,
            const float* __restrict__ ab2,  const float* __restrict__ aW3,
            const float* __restrict__ ab3,  const int* __restrict__ srcI,
            const int* __restrict__ dstI) {
    extern __shared__ float sm[];
    float* eaT  = sm;                    // [32][ASTE]
    float* eshT = eaT  + 32 * ASTE;      // [16][ASTE]
    float* hS   = eshT + 16 * ASTE;      // [128][ASTE]  (single, reused)
    float* Ws   = hS   + 128 * ASTE;     // [NBUF][KC][128]
    int*   sIdx = (int*)(Ws + NBUF * KC * 128);   // [128]
    int*   dIdx = sIdx + TILE_E;                  // [128]

    const int tid = threadIdx.x;
    const long e0 = (long)blockIdx.x * TILE_E;
    const int colg = tid & 31;
    const int rowb = (tid >> 5) * 8;
    const float* aW1c = aW1 + 128 * 128;   // edge-attr slice of aW1 (K=32)

    int pb = 0;
    prefetch_chunk<NTE>(fc1, 32, Ws, tid);

    if (tid < TILE_E)                sIdx[tid]          = srcI[e0 + tid];
    else if (tid < 2 * TILE_E)       dIdx[tid - TILE_E] = dstI[e0 + tid - TILE_E];

    for (int i = tid; i < TILE_E * 32; i += NTE) {
        int e = i >> 5, c = i & 31;
        eaT[c * ASTE + e] = ea[(size_t)(e0 + e) * 32 + c];
    }
    for (int i = tid; i < TILE_E * 16; i += NTE) {
        int e = i >> 4, c = i & 15;
        eshT[c * ASTE + e] = esh[(size_t)(e0 + e) * 16 + c];
    }

    unsigned long long acc[4][4];

    // ---- radial MLP: ea -> fc1 -> fc2 -> fc3 = scale (regs) ----
    gemm_stage<NTE, ASTE>(fc1, 32, eaT, Ws, acc, tid, true, pb, fc2, 128);
    store_act<ASTE>(acc, hS, b1, tid);                 // h := silu(fc1)
    gemm_stage<NTE, ASTE>(fc2, 128, hS, Ws, acc, tid, true, pb, fc3, 128);
    __syncthreads();                                   // h reread below
    store_act<ASTE>(acc, hS, b2, tid);                 // h := silu(fc2)
    gemm_stage<NTE, ASTE>(fc3, 128, hS, Ws, acc, tid, true, pb, W_sh, 16);

    float2 scale[4][4];
    {
        float bb[4];
#pragma unroll
        for (int c = 0; c < 4; c++) bb[c] = b3[colg + 32 * c];
#pragma unroll
        for (int rp = 0; rp < 4; rp++)
#pragma unroll
            for (int c = 0; c < 4; c++) {
                float2 v = unpack2(acc[rp][c]);
                scale[rp][c].x = v.x + bb[c];
                scale[rp][c].y = v.y + bb[c];
            }
    }

    // ---- msg = silu(T[src]*scale + sh @ W_sh) ----
    gemm_stage<NTE, ASTE>(W_sh, 16, eshT, Ws, acc, tid, true, pb, aW1c, 32);
#pragma unroll
    for (int rp = 0; rp < 4; rp++) {
        int r0 = rowb + 2 * rp;
        const float* t0 = g_T + (size_t)sIdx[r0] * 128 + colg;
        const float* t1 = g_T + (size_t)sIdx[r0 + 1] * 128 + colg;
        float* m0 = g_msg + (size_t)(e0 + r0) * 128 + colg;
        float* m1 = g_msg + (size_t)(e0 + r0 + 1) * 128 + colg;
#pragma unroll
        for (int c = 0; c < 4; c++) {
            float2 s = unpack2(acc[rp][c]);
            m0[32 * c] = silu_f(t0[32 * c] * scale[rp][c].x + s.x);
            m1[32 * c] = silu_f(t1[32 * c] * scale[rp][c].y + s.y);
        }
    }

    // ---- attention: acc = P[src] + Q[dst]; += ea @ aW1c; silu -> h ----
#pragma unroll
    for (int rp = 0; rp < 4; rp++) {
        int r0 = rowb + 2 * rp;
        const float* p0 = g_P + (size_t)sIdx[r0] * 128 + colg;
        const float* q0 = g_Q + (size_t)dIdx[r0] * 128 + colg;
        const float* p1 = g_P + (size_t)sIdx[r0 + 1] * 128 + colg;
        const float* q1 = g_Q + (size_t)dIdx[r0 + 1] * 128 + colg;
#pragma unroll
        for (int c = 0; c < 4; c++)
            acc[rp][c] = pack2(p0[32 * c] + q0[32 * c], p1[32 * c] + q1[32 * c]);
    }
    gemm_stage<NTE, ASTE>(aW1c, 32, eaT, Ws, acc, tid, false, pb, aW2, 128);
    store_act<ASTE>(acc, hS, ab1, tid);                // h := silu(alpha1)
    gemm_stage<NTE, ASTE>(aW2, 128, hS, Ws, acc, tid, true, pb, aW3, 8);
    __syncthreads();                                   // h reread below
    store_act<ASTE>(acc, hS, ab2, tid);                // h := silu(alpha2)

    // ---- aW3: [128 edges][128] @ [128][8]  (weights in ring slot pb) ----
    CP_WAIT(0);
    __syncthreads();
    {
        const float* W3 = Ws + pb * (KC * 128);
        int e  = tid & (TILE_E - 1);
        int ph = tid >> 7;        // 0..3 -> heads {2ph, 2ph+1}
        float a0 = 0.0f, a1 = 0.0f;
#pragma unroll 8
        for (int k = 0; k < 128; k++) {
            float av = hS[k * ASTE + e];
            a0 += av * W3[k * 8 + ph * 2];
            a1 += av * W3[k * 8 + ph * 2 + 1];
        }
        g_a[(size_t)(e0 + e) * 8 + ph * 2]     = a0 + ab3[ph * 2];
        g_a[(size_t)(e0 + e) * 8 + ph * 2 + 1] = a1 + ab3[ph * 2 + 1];
    }
}

// ---------------- softmax reductions -----------------------------------------
__global__ void max_kernel() {
    __shared__ float smem[256];
    int tid = threadIdx.x;
    float mx = -3.4e38f;
    long stride = (long)gridDim.x * 256;
    for (long i = (long)blockIdx.x * 256 + tid; i < (long)EE * HH; i += stride)
        mx = fmaxf(mx, g_a[i]);
    smem[tid] = mx; __syncthreads();
    for (int s = 128; s >= 8; s >>= 1) {
        if (tid < s) smem[tid] = fmaxf(smem[tid], smem[tid + s]);
        __syncthreads();
    }
    if (tid < 8) atomicMaxFloat(&g_max[tid], smem[tid]);
}
__global__ void sum_kernel() {
    __shared__ float smem[256];
    int tid = threadIdx.x;
    int h = tid & 7;
    float mx = g_max[h];
    float s = 0.0f;
    long stride = (long)gridDim.x * 256;
    for (long i = (long)blockIdx.x * 256 + tid; i < (long)EE * HH; i += stride)
        s += __expf(g_a[i] - mx);
    smem[tid] = s; __syncthreads();
    for (int t = 128; t >= 8; t >>= 1) {
        if (tid < t) smem[tid] += smem[tid + t];
        __syncthreads();
    }
    if (tid < 8) atomicAdd(&g_sum[tid], smem[tid]);
}
__global__ void alpha_kernel() {
    __shared__ float smx[8], sinv[8];
    int tid = threadIdx.x;
    if (tid < 8) { smx[tid] = g_max[tid]; sinv[tid] = 1.0f / g_sum[tid]; }
    __syncthreads();
    int e = blockIdx.x * 256 + tid;
    if (e >= EE) return;
    float4 a0 = *(const float4*)(g_a + (size_t)e * 8);
    float4 a1 = *(const float4*)(g_a + (size_t)e * 8 + 4);
    float p = __expf(a0.x - smx[0]) * sinv[0] + __expf(a0.y - smx[1]) * sinv[1]
            + __expf(a0.z - smx[2]) * sinv[2] + __expf(a0.w - smx[3]) * sinv[3]
            + __expf(a1.x - smx[4]) * sinv[4] + __expf(a1.y - smx[5]) * sinv[5]
            + __expf(a1.z - smx[6]) * sinv[6] + __expf(a1.w - smx[7]) * sinv[7];
    g_alpha[e] = p * 0.125f;
}

// ---------------- weighted scatter-add (vectorized red) ------------------------
__global__ void scatter_kernel(const int* __restrict__ dstI) {
    size_t i = (size_t)blockIdx.x * 256 + threadIdx.x;
    if (i >= (size_t)EE * 32) return;
    int e = (int)(i >> 5);
    int q = (int)(i & 31);
    float am = g_alpha[e];
    float4 v = *(const float4*)(g_msg + (size_t)e * 128 + q * 4);
    float* base = g_agg + (size_t)dstI[e] * 128 + q * 4;
    asm volatile("red.global.add.v4.f32 [%0], {%1, %2, %3, %4};"
                 :: "l"(base), "f"(v.x * am), "f"(v.y * am),
                    "f"(v.z * am), "f"(v.w * am) : "memory");
}

// ---------------- out = LN(nf + agg @ W_out) -----------------------------------
__global__ void __launch_bounds__(NTP, 1)
node_kernel(const float* __restrict__ nf, const float* __restrict__ W_out,
            float* __restrict__ out) {
    extern __shared__ float sm[];
    float* aggT = sm;                  // [128][ASTP]
    float* Ws   = sm + 128 * ASTP;     // [NBUF][KC][128]
    const int tid = threadIdx.x;
    const int n0 = blockIdx.x * 64;
    int nv = NN - n0; if (nv > 64) nv = 64;

    int pb = 0;
    prefetch_chunk<NTP>(W_out, KC, Ws, tid);

    for (int i = tid; i < 64 * 128; i += NTP) {
        int r = i >> 7, d = i & 127;
        aggT[d * ASTP + r] = (r < nv) ? g_agg[(size_t)(n0 + r) * 128 + d] : 0.0f;
    }

    unsigned long long acc[4][4];
    gemm_stage<NTP, ASTP>(W_out, 128, aggT, Ws, acc, tid, true, pb, nullptr, 0);

    const int colg = tid & 31;
    const int rowb = (tid >> 5) * 8;
#pragma unroll
    for (int rp = 0; rp < 4; rp++) {
        float2 v[4];
#pragma unroll
        for (int c = 0; c < 4; c++) v[c] = unpack2(acc[rp][c]);
#pragma unroll
        for (int half = 0; half < 2; half++) {
            int r = rowb + 2 * rp + half;
            int n = n0 + r;
            float x[4] = {0.f, 0.f, 0.f, 0.f};
            if (r < nv) {
                const float* xp = nf + (size_t)n * 128 + colg;
#pragma unroll
                for (int c = 0; c < 4; c++) x[c] = xp[32 * c];
            }
            float y[4];
#pragma unroll
            for (int c = 0; c < 4; c++)
                y[c] = x[c] + (half ? v[c].y : v[c].x);
            float s  = y[0] + y[1] + y[2] + y[3];
            float s2 = y[0]*y[0] + y[1]*y[1] + y[2]*y[2] + y[3]*y[3];
#pragma unroll
            for (int o = 16; o; o >>= 1) {
                s  += __shfl_xor_sync(0xffffffffu, s, o);
                s2 += __shfl_xor_sync(0xffffffffu, s2, o);
            }
            float mu  = s * (1.0f / 128.0f);
            float var = s2 * (1.0f / 128.0f) - mu * mu;
            float inv = rsqrtf(var + 1e-5f);
            if (r < nv) {
                float* op = out + (size_t)n * 128 + colg;
#pragma unroll
                for (int c = 0; c < 4; c++) op[32 * c] = (y[c] - mu) * inv;
            }
        }
    }
}

// ---------------- launch -----------------------------------------------------
extern "C" void kernel_launch(void* const* d_in, const int* in_sizes, int n_in,
                              void* d_out, int out_size) {
    const float* nf     = (const float*)d_in[0];
    const float* ea     = (const float*)d_in[1];
    const float* esh    = (const float*)d_in[2];
    const float* W_node = (const float*)d_in[3];
    const float* fc1    = (const float*)d_in[4];
    const float* b1     = (const float*)d_in[5];
    const float* fc2    = (const float*)d_in[6];
    const float* b2     = (const float*)d_in[7];
    const float* fc3    = (const float*)d_in[8];
    const float* b3     = (const float*)d_in[9];
    const float* W_sh   = (const float*)d_in[10];
    const float* aW1    = (const float*)d_in[11];
    const float* ab1    = (const float*)d_in[12];
    const float* aW2    = (const float*)d_in[13];
    const float* ab2    = (const float*)d_in[14];
    const float* aW3    = (const float*)d_in[15];
    const float* ab3    = (const float*)d_in[16];
    const float* W_out  = (const float*)d_in[17];
    const int*   eidx   = (const int*)d_in[18];
    const int*   srcI   = eidx;
    const int*   dstI   = eidx + EE;
    float* out = (float*)d_out;

    const int SMEM_PREP = (128 * ASTP + NBUF * KC * 128) * 4;
    const int SMEM_EDGE = ((32 + 16 + 128) * ASTE + NBUF * KC * 128) * 4
                          + 2 * TILE_E * (int)sizeof(int);
    const int SMEM_NODE = (128 * ASTP + NBUF * KC * 128) * 4;
    cudaFuncSetAttribute(prep_kernel, cudaFuncAttributeMaxDynamicSharedMemorySize, SMEM_PREP);
    cudaFuncSetAttribute(edge_kernel, cudaFuncAttributeMaxDynamicSharedMemorySize, SMEM_EDGE);
    cudaFuncSetAttribute(node_kernel, cudaFuncAttributeMaxDynamicSharedMemorySize, SMEM_NODE);

    zero_agg<<<(NN * DD + 255) / 256, 256>>>();
    zero_heads<<<1, 32>>>();
    prep_kernel<<<(NN + 63) / 64, NTP, SMEM_PREP>>>(nf, W_node, aW1);
    edge_kernel<<<EE / TILE_E, NTE, SMEM_EDGE>>>(ea, esh,
                                                 fc1, b1, fc2, b2, fc3, b3,
                                                 W_sh, aW1, ab1, aW2, ab2,
                                                 aW3, ab3, srcI, dstI);
    max_kernel<<<512, 256>>>();
    sum_kernel<<<512, 256>>>();
    alpha_kernel<<<(EE + 255) / 256, 256>>>();
    scatter_kernel<<<(int)(((size_t)EE * 32 + 255) / 256), 256>>>(dstI);
    node_kernel<<<(NN + 63) / 64, NTP, SMEM_NODE>>>(nf, W_out, out);
}

// round 15
// speedup vs baseline: 1.1686x; 1.1686x over previous
#include <cuda_runtime.h>
#include <cstdint>
#include <cstddef>

// Problem constants
#define NN   50000
#define EE   800000
#define DD   128
#define HH   8

#define KC     64    // weight K-chunk staged in SMEM
#define NBUF   3     // weight ring slots

// edge kernel geometry
#define TILE_E 128
#define NTE    512
#define ASTE   132   // SMEM activation stride for 128-row tiles

// prep/node kernel geometry
#define NTP    256
#define ASTP   68

// Row-swizzle for transposed activation buffers: rows permuted in 4-row groups
// by column. Kills the 16-way STS conflict in epilogues at zero instruction cost.
#define SWX(j)      ((((j) >> 2) & 7) << 2)
#define SWR(j, r)   ((r) ^ SWX(j))

// ---------------- scratch (device globals: no allocation allowed) ----------
__device__ float g_msg[(size_t)EE * DD];      // 409.6 MB
__device__ float g_a[(size_t)EE * HH];        // 25.6 MB
__device__ float g_alpha[EE];                 // 3.2 MB
__device__ float g_agg[(size_t)NN * DD];      // 25.6 MB
__device__ float g_T[(size_t)NN * DD];        // nf @ W_node
__device__ float g_P[(size_t)NN * DD];        // nf[:, :64] @ aW1[0:64]
__device__ float g_Q[(size_t)NN * DD];        // nf[:, :64] @ aW1[64:128]
__device__ float g_max[HH];
__device__ float g_sum[HH];

// ---------------- helpers ---------------------------------------------------
__device__ __forceinline__ unsigned long long pack2(float x, float y) {
    unsigned long long r;
    asm("mov.b64 %0, {%1, %2};" : "=l"(r) : "f"(x), "f"(y));
    return r;
}
__device__ __forceinline__ float2 unpack2(unsigned long long v) {
    float2 f;
    asm("mov.b64 {%0, %1}, %2;" : "=f"(f.x), "=f"(f.y) : "l"(v));
    return f;
}
__device__ __forceinline__ void ffma2(unsigned long long& d,
                                      unsigned long long a,
                                      unsigned long long b) {
    asm("fma.rn.f32x2 %0, %1, %2, %0;" : "+l"(d) : "l"(a), "l"(b));
}
__device__ __forceinline__ float silu_f(float x) {
    return x / (1.0f + __expf(-x));
}
__device__ __forceinline__ void atomicMaxFloat(float* addr, float v) {
    if (v >= 0.0f) atomicMax((int*)addr, __float_as_int(v));
    else           atomicMin((unsigned int*)addr, __float_as_uint(v));
}

// ---------------- async copy -------------------------------------------------
__device__ __forceinline__ void cp_async16(void* sdst, const void* gsrc) {
    uint32_t s = (uint32_t)__cvta_generic_to_shared(sdst);
    asm volatile("cp.async.cg.shared.global [%0], [%1], 16;" :: "r"(s), "l"(gsrc));
}
#define CP_COMMIT() asm volatile("cp.async.commit_group;" ::: "memory")
#define CP_WAIT(n)  asm volatile("cp.async.wait_group %0;" :: "n"(n) : "memory")

template<int NT>
__device__ __forceinline__ void prefetch_chunk(const float* __restrict__ W,
                                               int rows, float* __restrict__ dst,
                                               int tid) {
    const float4* s = (const float4*)W;
    float4* d = (float4*)dst;
    int n = rows * 32;
    for (int i = tid; i < n; i += NT) cp_async16(d + i, s + i);
    CP_COMMIT();
}

// ---------------- GEMM core -------------------------------------------------
// C[ROWS x 128] += A_s[K][AS] (smem, transposed+row-swizzled) * Wg[K][128].
// ROWS = NT/4 (each warp owns 8 rows). Weights stream through the 3-slot
// cp.async ring; chunk0 of this stage must already be in slot pb; during the
// last chunk the first chunk of the next stage is prefetched.
template<int NT, int AS>
__device__ __forceinline__ void gemm_stage(const float* __restrict__ Wg, int K,
                                           const float* __restrict__ As,
                                           float* __restrict__ WsBase,
                                           unsigned long long (&acc)[4][4],
                                           int tid, bool zinit, int& pb,
                                           const float* __restrict__ nxtW,
                                           int nxtRows) {
    const int colg = tid & 31;
    const int rowb = (tid >> 5) * 8;
    if (zinit) {
#pragma unroll
        for (int rp = 0; rp < 4; rp++)
#pragma unroll
            for (int c = 0; c < 4; c++) acc[rp][c] = 0ull;
    }
    const int nc = (K + KC - 1) / KC;
    for (int c = 0; c < nc; c++) {
        if (c + 1 < nc) {
            int k0n = (c + 1) * KC;
            int rn = K - k0n; if (rn > KC) rn = KC;
            prefetch_chunk<NT>(Wg + (size_t)k0n * 128, rn,
                               WsBase + ((pb + 1) % NBUF) * (KC * 128), tid);
            CP_WAIT(1);
        } else if (nxtW) {
            int rn = nxtRows > KC ? KC : nxtRows;
            prefetch_chunk<NT>(nxtW, rn,
                               WsBase + ((pb + 1) % NBUF) * (KC * 128), tid);
            CP_WAIT(1);
        } else {
            CP_WAIT(0);
        }
        __syncthreads();
        const float* Ws = WsBase + pb * (KC * 128);
        int k0 = c * KC;
        int kc = K - k0; if (kc > KC) kc = KC;
#pragma unroll 4
        for (int k = 0; k < kc; k++) {
            const int kk = k0 + k;
            const float* Ak = As + kk * AS;
            const int sx = SWX(kk);
            ulonglong2 a01 = *(const ulonglong2*)(Ak + (rowb ^ sx));
            ulonglong2 a23 = *(const ulonglong2*)(Ak + ((rowb + 4) ^ sx));
            float4 w = *(const float4*)(Ws + k * 128 + colg * 4);
            unsigned long long w2[4];
            w2[0] = pack2(w.x, w.x); w2[1] = pack2(w.y, w.y);
            w2[2] = pack2(w.z, w.z); w2[3] = pack2(w.w, w.w);
#pragma unroll
            for (int cc = 0; cc < 4; cc++) {
                ffma2(acc[0][cc], a01.x, w2[cc]);
                ffma2(acc[1][cc], a01.y, w2[cc]);
                ffma2(acc[2][cc], a23.x, w2[cc]);
                ffma2(acc[3][cc], a23.y, w2[cc]);
            }
        }
        pb = (pb + 1) % NBUF;
    }
}

// epilogue: silu(acc + bias) written transposed (row-swizzled) to an
// activation buffer. Swizzle spreads the former 16-way STS conflict to 4-way.
template<int AS>
__device__ __forceinline__ void store_act(unsigned long long (&acc)[4][4],
                                          float* __restrict__ AsOut,
                                          const float* __restrict__ bias,
                                          int tid) {
    const int colg = tid & 31;
    const int rowb = (tid >> 5) * 8;
    const int sx = (colg & 7) << 2;      // SWX(colg*4+c), c<4
    float4 b4 = *(const float4*)(bias + colg * 4);
    float bb[4] = {b4.x, b4.y, b4.z, b4.w};
#pragma unroll
    for (int rp = 0; rp < 4; rp++)
#pragma unroll
        for (int c = 0; c < 4; c++) {
            float2 v = unpack2(acc[rp][c]);
            v.x = silu_f(v.x + bb[c]);
            v.y = silu_f(v.y + bb[c]);
            *(float2*)(AsOut + (colg * 4 + c) * AS + ((rowb + 2 * rp) ^ sx)) = v;
        }
}

// plain store of acc to global [row][128]
__device__ __forceinline__ void store_global(unsigned long long (&acc)[4][4],
                                             float* __restrict__ G,
                                             long r0base, int nv, int tid) {
    const int colg = tid & 31;
    const int rowb = (tid >> 5) * 8;
#pragma unroll
    for (int rp = 0; rp < 4; rp++) {
        float2 v[4];
#pragma unroll
        for (int c = 0; c < 4; c++) v[c] = unpack2(acc[rp][c]);
        int r0 = rowb + 2 * rp;
        if (r0 < nv)
            *(float4*)(G + (size_t)(r0base + r0) * 128 + colg * 4) =
                make_float4(v[0].x, v[1].x, v[2].x, v[3].x);
        if (r0 + 1 < nv)
            *(float4*)(G + (size_t)(r0base + r0 + 1) * 128 + colg * 4) =
                make_float4(v[0].y, v[1].y, v[2].y, v[3].y);
    }
}

// ---------------- init scratch -----------------------------------------------
__global__ void zero_agg() {
    int i = blockIdx.x * 256 + threadIdx.x;
    if (i < NN * DD) g_agg[i] = 0.0f;
}
__global__ void zero_heads() {
    int i = threadIdx.x;
    if (i < HH) { g_max[i] = -3.4e38f; g_sum[i] = 0.0f; }
}

// ---------------- per-node precompute ----------------------------------------
// T = nf @ W_node ; P = nf[:, :64] @ aW1[0:64] ; Q = nf[:, :64] @ aW1[64:128]
__global__ void __launch_bounds__(NTP, 1)
prep_kernel(const float* __restrict__ nf, const float* __restrict__ W_node,
            const float* __restrict__ aW1) {
    extern __shared__ float sm[];
    float* nfT = sm;                  // [128][ASTP]
    float* Ws  = sm + 128 * ASTP;     // [NBUF][KC][128]
    const int tid = threadIdx.x;
    const long n0 = (long)blockIdx.x * 64;
    int nv = (int)(NN - n0); if (nv > 64) nv = 64;

    int pb = 0;
    prefetch_chunk<NTP>(W_node, KC, Ws, tid);

    for (int i = tid; i < 64 * 128; i += NTP) {
        int r = i >> 7, d = i & 127;
        nfT[d * ASTP + SWR(d, r)] = (r < nv) ? nf[(size_t)(n0 + r) * 128 + d] : 0.0f;
    }

    unsigned long long acc[4][4];
    gemm_stage<NTP, ASTP>(W_node, 128, nfT, Ws, acc, tid, true, pb, aW1, 64);
    store_global(acc, g_T, n0, nv, tid);
    gemm_stage<NTP, ASTP>(aW1, 64, nfT, Ws, acc, tid, true, pb, aW1 + 64 * 128, 64);
    store_global(acc, g_P, n0, nv, tid);
    gemm_stage<NTP, ASTP>(aW1 + 64 * 128, 64, nfT, Ws, acc, tid, true, pb, nullptr, 0);
    store_global(acc, g_Q, n0, nv, tid);
}

// ---------------- per-edge fused pipeline -------------------------------------
__global__ void __launch_bounds__(NTE, 1)
edge_kernel(const float* __restrict__ ea,   const float* __restrict__ esh,
            const float* __restrict__ fc1,  const float* __restrict__ b1,
            const float* __restrict__ fc2,  const float* __restrict__ b2,
            const float* __restrict__ fc3,  const float* __restrict__ b3,
            const float* __restrict__ W_sh, const float* __restrict__ aW1,
            const float* __restrict__ ab1,  const float* __restrict__ aW2,
            const float* __restrict__ ab2,  const float* __restrict__ aW3,
            const float* __restrict__ ab3,  const int* __restrict__ srcI,
            const int* __restrict__ dstI) {
    extern __shared__ float sm[];
    float* eaT  = sm;                    // [32][ASTE]
    float* eshT = eaT  + 32 * ASTE;      // [16][ASTE]
    float* hS   = eshT + 16 * ASTE;      // [128][ASTE]  (single, reused)
    float* Ws   = hS   + 128 * ASTE;     // [NBUF][KC][128]
    int*   sIdx = (int*)(Ws + NBUF * KC * 128);   // [128]
    int*   dIdx = sIdx + TILE_E;                  // [128]

    const int tid = threadIdx.x;
    const long e0 = (long)blockIdx.x * TILE_E;
    const int colg = tid & 31;
    const int rowb = (tid >> 5) * 8;
    const float* aW1c = aW1 + 128 * 128;   // edge-attr slice of aW1 (K=32)

    int pb = 0;
    prefetch_chunk<NTE>(fc1, 32, Ws, tid);

    if (tid < TILE_E)                sIdx[tid]          = srcI[e0 + tid];
    else if (tid < 2 * TILE_E)       dIdx[tid - TILE_E] = dstI[e0 + tid - TILE_E];

    for (int i = tid; i < TILE_E * 32; i += NTE) {
        int e = i >> 5, c = i & 31;
        eaT[c * ASTE + SWR(c, e)] = ea[(size_t)(e0 + e) * 32 + c];
    }
    for (int i = tid; i < TILE_E * 16; i += NTE) {
        int e = i >> 4, c = i & 15;
        eshT[c * ASTE + SWR(c, e)] = esh[(size_t)(e0 + e) * 16 + c];
    }

    unsigned long long acc[4][4];

    // ---- radial MLP: ea -> fc1 -> fc2 -> fc3 = scale (regs) ----
    gemm_stage<NTE, ASTE>(fc1, 32, eaT, Ws, acc, tid, true, pb, fc2, 128);
    store_act<ASTE>(acc, hS, b1, tid);                 // h := silu(fc1)
    gemm_stage<NTE, ASTE>(fc2, 128, hS, Ws, acc, tid, true, pb, fc3, 128);
    __syncthreads();                                   // h reread below
    store_act<ASTE>(acc, hS, b2, tid);                 // h := silu(fc2)
    gemm_stage<NTE, ASTE>(fc3, 128, hS, Ws, acc, tid, true, pb, W_sh, 16);

    float2 scale[4][4];
    {
        float4 b4 = *(const float4*)(b3 + colg * 4);
        float bb[4] = {b4.x, b4.y, b4.z, b4.w};
#pragma unroll
        for (int rp = 0; rp < 4; rp++)
#pragma unroll
            for (int c = 0; c < 4; c++) {
                float2 v = unpack2(acc[rp][c]);
                scale[rp][c].x = v.x + bb[c];
                scale[rp][c].y = v.y + bb[c];
            }
    }

    // ---- msg = silu(T[src]*scale + sh @ W_sh) ----
    gemm_stage<NTE, ASTE>(W_sh, 16, eshT, Ws, acc, tid, true, pb, aW1c, 32);
#pragma unroll
    for (int rp = 0; rp < 4; rp++) {
        int r0 = rowb + 2 * rp;
        float4 t0 = *(const float4*)(g_T + (size_t)sIdx[r0] * 128 + colg * 4);
        float4 t1 = *(const float4*)(g_T + (size_t)sIdx[r0 + 1] * 128 + colg * 4);
        float tA[4] = {t0.x, t0.y, t0.z, t0.w};
        float tB[4] = {t1.x, t1.y, t1.z, t1.w};
        float o0[4], o1[4];
#pragma unroll
        for (int c = 0; c < 4; c++) {
            float2 s = unpack2(acc[rp][c]);
            o0[c] = silu_f(tA[c] * scale[rp][c].x + s.x);
            o1[c] = silu_f(tB[c] * scale[rp][c].y + s.y);
        }
        *(float4*)(g_msg + (size_t)(e0 + r0) * 128 + colg * 4) =
            make_float4(o0[0], o0[1], o0[2], o0[3]);
        *(float4*)(g_msg + (size_t)(e0 + r0 + 1) * 128 + colg * 4) =
            make_float4(o1[0], o1[1], o1[2], o1[3]);
    }

    // ---- attention: acc = P[src] + Q[dst]; += ea @ aW1c; silu -> h ----
#pragma unroll
    for (int rp = 0; rp < 4; rp++) {
        int r0 = rowb + 2 * rp;
        float4 p0 = *(const float4*)(g_P + (size_t)sIdx[r0] * 128 + colg * 4);
        float4 q0 = *(const float4*)(g_Q + (size_t)dIdx[r0] * 128 + colg * 4);
        float4 p1 = *(const float4*)(g_P + (size_t)sIdx[r0 + 1] * 128 + colg * 4);
        float4 q1 = *(const float4*)(g_Q + (size_t)dIdx[r0 + 1] * 128 + colg * 4);
        acc[rp][0] = pack2(p0.x + q0.x, p1.x + q1.x);
        acc[rp][1] = pack2(p0.y + q0.y, p1.y + q1.y);
        acc[rp][2] = pack2(p0.z + q0.z, p1.z + q1.z);
        acc[rp][3] = pack2(p0.w + q0.w, p1.w + q1.w);
    }
    gemm_stage<NTE, ASTE>(aW1c, 32, eaT, Ws, acc, tid, false, pb, aW2, 128);
    store_act<ASTE>(acc, hS, ab1, tid);                // h := silu(alpha1)
    gemm_stage<NTE, ASTE>(aW2, 128, hS, Ws, acc, tid, true, pb, aW3, 8);
    __syncthreads();                                   // h reread below
    store_act<ASTE>(acc, hS, ab2, tid);                // h := silu(alpha2)

    // ---- aW3: [128 edges][128] @ [128][8]  (weights in ring slot pb) ----
    CP_WAIT(0);
    __syncthreads();
    {
        const float* W3 = Ws + pb * (KC * 128);
        int e  = tid & (TILE_E - 1);
        int ph = tid >> 7;        // 0..3 -> heads {2ph, 2ph+1}
        float a0 = 0.0f, a1 = 0.0f;
#pragma unroll 8
        for (int k = 0; k < 128; k++) {
            float av = hS[k * ASTE + SWR(k, e)];
            a0 += av * W3[k * 8 + ph * 2];
            a1 += av * W3[k * 8 + ph * 2 + 1];
        }
        g_a[(size_t)(e0 + e) * 8 + ph * 2]     = a0 + ab3[ph * 2];
        g_a[(size_t)(e0 + e) * 8 + ph * 2 + 1] = a1 + ab3[ph * 2 + 1];
    }
}

// ---------------- softmax reductions -----------------------------------------
__global__ void max_kernel() {
    __shared__ float smem[256];
    int tid = threadIdx.x;
    float mx = -3.4e38f;
    long stride = (long)gridDim.x * 256;
    for (long i = (long)blockIdx.x * 256 + tid; i < (long)EE * HH; i += stride)
        mx = fmaxf(mx, g_a[i]);
    smem[tid] = mx; __syncthreads();
    for (int s = 128; s >= 8; s >>= 1) {
        if (tid < s) smem[tid] = fmaxf(smem[tid], smem[tid + s]);
        __syncthreads();
    }
    if (tid < 8) atomicMaxFloat(&g_max[tid], smem[tid]);
}
__global__ void sum_kernel() {
    __shared__ float smem[256];
    int tid = threadIdx.x;
    int h = tid & 7;
    float mx = g_max[h];
    float s = 0.0f;
    long stride = (long)gridDim.x * 256;
    for (long i = (long)blockIdx.x * 256 + tid; i < (long)EE * HH; i += stride)
        s += __expf(g_a[i] - mx);
    smem[tid] = s; __syncthreads();
    for (int t = 128; t >= 8; t >>= 1) {
        if (tid < t) smem[tid] += smem[tid + t];
        __syncthreads();
    }
    if (tid < 8) atomicAdd(&g_sum[tid], smem[tid]);
}
__global__ void alpha_kernel() {
    __shared__ float smx[8], sinv[8];
    int tid = threadIdx.x;
    if (tid < 8) { smx[tid] = g_max[tid]; sinv[tid] = 1.0f / g_sum[tid]; }
    __syncthreads();
    int e = blockIdx.x * 256 + tid;
    if (e >= EE) return;
    float4 a0 = *(const float4*)(g_a + (size_t)e * 8);
    float4 a1 = *(const float4*)(g_a + (size_t)e * 8 + 4);
    float p = __expf(a0.x - smx[0]) * sinv[0] + __expf(a0.y - smx[1]) * sinv[1]
            + __expf(a0.z - smx[2]) * sinv[2] + __expf(a0.w - smx[3]) * sinv[3]
            + __expf(a1.x - smx[4]) * sinv[4] + __expf(a1.y - smx[5]) * sinv[5]
            + __expf(a1.z - smx[6]) * sinv[6] + __expf(a1.w - smx[7]) * sinv[7];
    g_alpha[e] = p * 0.125f;
}

// ---------------- weighted scatter-add (vectorized red) ------------------------
__global__ void scatter_kernel(const int* __restrict__ dstI) {
    size_t i = (size_t)blockIdx.x * 256 + threadIdx.x;
    if (i >= (size_t)EE * 32) return;
    int e = (int)(i >> 5);
    int q = (int)(i & 31);
    float am = g_alpha[e];
    float4 v = *(const float4*)(g_msg + (size_t)e * 128 + q * 4);
    float* base = g_agg + (size_t)dstI[e] * 128 + q * 4;
    asm volatile("red.global.add.v4.f32 [%0], {%1, %2, %3, %4};"
                 :: "l"(base), "f"(v.x * am), "f"(v.y * am),
                    "f"(v.z * am), "f"(v.w * am) : "memory");
}

// ---------------- out = LN(nf + agg @ W_out) -----------------------------------
__global__ void __launch_bounds__(NTP, 1)
node_kernel(const float* __restrict__ nf, const float* __restrict__ W_out,
            float* __restrict__ out) {
    extern __shared__ float sm[];
    float* aggT = sm;                  // [128][ASTP]
    float* Ws   = sm + 128 * ASTP;     // [NBUF][KC][128]
    const int tid = threadIdx.x;
    const int n0 = blockIdx.x * 64;
    int nv = NN - n0; if (nv > 64) nv = 64;

    int pb = 0;
    prefetch_chunk<NTP>(W_out, KC, Ws, tid);

    for (int i = tid; i < 64 * 128; i += NTP) {
        int r = i >> 7, d = i & 127;
        aggT[d * ASTP + SWR(d, r)] = (r < nv) ? g_agg[(size_t)(n0 + r) * 128 + d] : 0.0f;
    }

    unsigned long long acc[4][4];
    gemm_stage<NTP, ASTP>(W_out, 128, aggT, Ws, acc, tid, true, pb, nullptr, 0);

    const int colg = tid & 31;
    const int rowb = (tid >> 5) * 8;
#pragma unroll
    for (int rp = 0; rp < 4; rp++) {
        float2 v[4];
#pragma unroll
        for (int c = 0; c < 4; c++) v[c] = unpack2(acc[rp][c]);
#pragma unroll
        for (int half = 0; half < 2; half++) {
            int r = rowb + 2 * rp + half;
            int n = n0 + r;
            float4 x = make_float4(0.f, 0.f, 0.f, 0.f);
            if (r < nv) x = *(const float4*)(nf + (size_t)n * 128 + colg * 4);
            float y0 = x.x + (half ? v[0].y : v[0].x);
            float y1 = x.y + (half ? v[1].y : v[1].x);
            float y2 = x.z + (half ? v[2].y : v[2].x);
            float y3 = x.w + (half ? v[3].y : v[3].x);
            float s  = y0 + y1 + y2 + y3;
            float s2 = y0 * y0 + y1 * y1 + y2 * y2 + y3 * y3;
#pragma unroll
            for (int o = 16; o; o >>= 1) {
                s  += __shfl_xor_sync(0xffffffffu, s, o);
                s2 += __shfl_xor_sync(0xffffffffu, s2, o);
            }
            float mu  = s * (1.0f / 128.0f);
            float var = s2 * (1.0f / 128.0f) - mu * mu;
            float inv = rsqrtf(var + 1e-5f);
            if (r < nv) {
                *(float4*)(out + (size_t)n * 128 + colg * 4) =
                    make_float4((y0 - mu) * inv, (y1 - mu) * inv,
                                (y2 - mu) * inv, (y3 - mu) * inv);
            }
        }
    }
}

// ---------------- launch -----------------------------------------------------
extern "C" void kernel_launch(void* const* d_in, const int* in_sizes, int n_in,
                              void* d_out, int out_size) {
    const float* nf     = (const float*)d_in[0];
    const float* ea     = (const float*)d_in[1];
    const float* esh    = (const float*)d_in[2];
    const float* W_node = (const float*)d_in[3];
    const float* fc1    = (const float*)d_in[4];
    const float* b1     = (const float*)d_in[5];
    const float* fc2    = (const float*)d_in[6];
    const float* b2     = (const float*)d_in[7];
    const float* fc3    = (const float*)d_in[8];
    const float* b3     = (const float*)d_in[9];
    const float* W_sh   = (const float*)d_in[10];
    const float* aW1    = (const float*)d_in[11];
    const float* ab1    = (const float*)d_in[12];
    const float* aW2    = (const float*)d_in[13];
    const float* ab2    = (const float*)d_in[14];
    const float* aW3    = (const float*)d_in[15];
    const float* ab3    = (const float*)d_in[16];
    const float* W_out  = (const float*)d_in[17];
    const int*   eidx   = (const int*)d_in[18];
    const int*   srcI   = eidx;
    const int*   dstI   = eidx + EE;
    float* out = (float*)d_out;

    const int SMEM_PREP = (128 * ASTP + NBUF * KC * 128) * 4;
    const int SMEM_EDGE = ((32 + 16 + 128) * ASTE + NBUF * KC * 128) * 4
                          + 2 * TILE_E * (int)sizeof(int);
    const int SMEM_NODE = (128 * ASTP + NBUF * KC * 128) * 4;
    cudaFuncSetAttribute(prep_kernel, cudaFuncAttributeMaxDynamicSharedMemorySize, SMEM_PREP);
    cudaFuncSetAttribute(edge_kernel, cudaFuncAttributeMaxDynamicSharedMemorySize, SMEM_EDGE);
    cudaFuncSetAttribute(node_kernel, cudaFuncAttributeMaxDynamicSharedMemorySize, SMEM_NODE);

    zero_agg<<<(NN * DD + 255) / 256, 256>>>();
    zero_heads<<<1, 32>>>();
    prep_kernel<<<(NN + 63) / 64, NTP, SMEM_PREP>>>(nf, W_node, aW1);
    edge_kernel<<<EE / TILE_E, NTE, SMEM_EDGE>>>(ea, esh,
                                                 fc1, b1, fc2, b2, fc3, b3,
                                                 W_sh, aW1, ab1, aW2, ab2,
                                                 aW3, ab3, srcI, dstI);
    max_kernel<<<512, 256>>>();
    sum_kernel<<<512, 256>>>();
    alpha_kernel<<<(EE + 255) / 256, 256>>>();
    scatter_kernel<<<(int)(((size_t)EE * 32 + 255) / 256), 256>>>(dstI);
    node_kernel<<<(NN + 63) / 64, NTP, SMEM_NODE>>>(nf, W_out, out);
}

// round 16
// speedup vs baseline: 1.2263x; 1.0493x over previous
#include <cuda_runtime.h>
#include <cstdint>
#include <cstddef>

// Problem constants
#define NN   50000
#define EE   800000
#define DD   128
#define HH   8

#define KC     64    // weight K-chunk staged in SMEM
#define NBUF   3     // weight ring slots

// edge kernel geometry
#define TILE_E 128
#define NTE    512
#define ASTE   132   // SMEM activation stride for 128-row tiles

// prep/node kernel geometry
#define NTP    256
#define ASTP   68

// Row-swizzle for transposed activation buffers: rows permuted in 4-row groups
// by column (period 32). Kills the 16-way STS conflict in epilogues.
#define SWX(j)      ((((j) >> 2) & 7) << 2)
#define SWR(j, r)   ((r) ^ SWX(j))

// ---------------- scratch (device globals: no allocation allowed) ----------
__device__ float g_msg[(size_t)EE * DD];      // 409.6 MB
__device__ float g_a[(size_t)EE * HH];        // 25.6 MB
__device__ float g_alpha[EE];                 // 3.2 MB
__device__ float g_agg[(size_t)NN * DD];      // 25.6 MB
__device__ float g_T[(size_t)NN * DD];        // nf @ W_node
__device__ float g_P[(size_t)NN * DD];        // nf[:, :64] @ aW1[0:64]
__device__ float g_Q[(size_t)NN * DD];        // nf[:, :64] @ aW1[64:128]
__device__ float g_max[HH];
__device__ float g_sum[HH];

// ---------------- helpers ---------------------------------------------------
__device__ __forceinline__ unsigned long long pack2(float x, float y) {
    unsigned long long r;
    asm("mov.b64 %0, {%1, %2};" : "=l"(r) : "f"(x), "f"(y));
    return r;
}
__device__ __forceinline__ float2 unpack2(unsigned long long v) {
    float2 f;
    asm("mov.b64 {%0, %1}, %2;" : "=f"(f.x), "=f"(f.y) : "l"(v));
    return f;
}
__device__ __forceinline__ void ffma2(unsigned long long& d,
                                      unsigned long long a,
                                      unsigned long long b) {
    asm("fma.rn.f32x2 %0, %1, %2, %0;" : "+l"(d) : "l"(a), "l"(b));
}
__device__ __forceinline__ float silu_f(float x) {
    return x / (1.0f + __expf(-x));
}
__device__ __forceinline__ void atomicMaxFloat(float* addr, float v) {
    if (v >= 0.0f) atomicMax((int*)addr, __float_as_int(v));
    else           atomicMin((unsigned int*)addr, __float_as_uint(v));
}

// ---------------- async copy -------------------------------------------------
__device__ __forceinline__ void cp_async16(void* sdst, const void* gsrc) {
    uint32_t s = (uint32_t)__cvta_generic_to_shared(sdst);
    asm volatile("cp.async.cg.shared.global [%0], [%1], 16;" :: "r"(s), "l"(gsrc));
}
#define CP_COMMIT() asm volatile("cp.async.commit_group;" ::: "memory")
#define CP_WAIT(n)  asm volatile("cp.async.wait_group %0;" :: "n"(n) : "memory")

template<int NT>
__device__ __forceinline__ void prefetch_chunk(const float* __restrict__ W,
                                               int rows, float* __restrict__ dst,
                                               int tid) {
    const float4* s = (const float4*)W;
    float4* d = (float4*)dst;
    int n = rows * 32;
    for (int i = tid; i < n; i += NT) cp_async16(d + i, s + i);
    CP_COMMIT();
}

// ---------------- GEMM core -------------------------------------------------
// C[ROWS x 128] += A_s[K][AS] (smem, transposed+row-swizzled) * Wg[K][128].
// k-loop runs in groups of 4 so the swizzle offset (constant within a group)
// is hoisted out: inner addressing is pure affine, zero extra ALU per k.
template<int NT, int AS>
__device__ __forceinline__ void gemm_stage(const float* __restrict__ Wg, int K,
                                           const float* __restrict__ As,
                                           float* __restrict__ WsBase,
                                           unsigned long long (&acc)[4][4],
                                           int tid, bool zinit, int& pb,
                                           const float* __restrict__ nxtW,
                                           int nxtRows) {
    const int colg = tid & 31;
    const int rowb = (tid >> 5) * 8;
    if (zinit) {
#pragma unroll
        for (int rp = 0; rp < 4; rp++)
#pragma unroll
            for (int c = 0; c < 4; c++) acc[rp][c] = 0ull;
    }
    const int nc = (K + KC - 1) / KC;
    for (int c = 0; c < nc; c++) {
        if (c + 1 < nc) {
            int k0n = (c + 1) * KC;
            int rn = K - k0n; if (rn > KC) rn = KC;
            prefetch_chunk<NT>(Wg + (size_t)k0n * 128, rn,
                               WsBase + ((pb + 1) % NBUF) * (KC * 128), tid);
            CP_WAIT(1);
        } else if (nxtW) {
            int rn = nxtRows > KC ? KC : nxtRows;
            prefetch_chunk<NT>(nxtW, rn,
                               WsBase + ((pb + 1) % NBUF) * (KC * 128), tid);
            CP_WAIT(1);
        } else {
            CP_WAIT(0);
        }
        __syncthreads();
        const float* Ws = WsBase + pb * (KC * 128);
        int k0 = c * KC;
        int kc = K - k0; if (kc > KC) kc = KC;
        // k in groups of 4: swizzle offset constant within a group
        for (int kg = 0; kg < kc; kg += 4) {
            const int sx = SWX(k0 + kg);
            const float* Ag = As + (k0 + kg) * AS;
            const float* A0 = Ag + (rowb ^ sx);
            const float* A1 = Ag + ((rowb + 4) ^ sx);
            const float* Wk = Ws + kg * 128 + colg * 4;
#pragma unroll
            for (int k4 = 0; k4 < 4; k4++) {
                ulonglong2 a01 = *(const ulonglong2*)(A0 + k4 * AS);
                ulonglong2 a23 = *(const ulonglong2*)(A1 + k4 * AS);
                float4 w = *(const float4*)(Wk + k4 * 128);
                unsigned long long w2[4];
                w2[0] = pack2(w.x, w.x); w2[1] = pack2(w.y, w.y);
                w2[2] = pack2(w.z, w.z); w2[3] = pack2(w.w, w.w);
#pragma unroll
                for (int cc = 0; cc < 4; cc++) {
                    ffma2(acc[0][cc], a01.x, w2[cc]);
                    ffma2(acc[1][cc], a01.y, w2[cc]);
                    ffma2(acc[2][cc], a23.x, w2[cc]);
                    ffma2(acc[3][cc], a23.y, w2[cc]);
                }
            }
        }
        pb = (pb + 1) % NBUF;
    }
}

// epilogue: silu(acc + bias) written transposed (row-swizzled) to an
// activation buffer. Swizzle spreads the former 16-way STS conflict to 4-way.
template<int AS>
__device__ __forceinline__ void store_act(unsigned long long (&acc)[4][4],
                                          float* __restrict__ AsOut,
                                          const float* __restrict__ bias,
                                          int tid) {
    const int colg = tid & 31;
    const int rowb = (tid >> 5) * 8;
    const int sx = (colg & 7) << 2;      // SWX(colg*4+c), c<4
    float4 b4 = *(const float4*)(bias + colg * 4);
    float bb[4] = {b4.x, b4.y, b4.z, b4.w};
#pragma unroll
    for (int rp = 0; rp < 4; rp++)
#pragma unroll
        for (int c = 0; c < 4; c++) {
            float2 v = unpack2(acc[rp][c]);
            v.x = silu_f(v.x + bb[c]);
            v.y = silu_f(v.y + bb[c]);
            *(float2*)(AsOut + (colg * 4 + c) * AS + ((rowb + 2 * rp) ^ sx)) = v;
        }
}

// plain store of acc to global [row][128]
__device__ __forceinline__ void store_global(unsigned long long (&acc)[4][4],
                                             float* __restrict__ G,
                                             long r0base, int nv, int tid) {
    const int colg = tid & 31;
    const int rowb = (tid >> 5) * 8;
#pragma unroll
    for (int rp = 0; rp < 4; rp++) {
        float2 v[4];
#pragma unroll
        for (int c = 0; c < 4; c++) v[c] = unpack2(acc[rp][c]);
        int r0 = rowb + 2 * rp;
        if (r0 < nv)
            *(float4*)(G + (size_t)(r0base + r0) * 128 + colg * 4) =
                make_float4(v[0].x, v[1].x, v[2].x, v[3].x);
        if (r0 + 1 < nv)
            *(float4*)(G + (size_t)(r0base + r0 + 1) * 128 + colg * 4) =
                make_float4(v[0].y, v[1].y, v[2].y, v[3].y);
    }
}

// ---------------- init scratch -----------------------------------------------
__global__ void zero_agg() {
    int i = blockIdx.x * 256 + threadIdx.x;
    if (i < NN * DD) g_agg[i] = 0.0f;
}
__global__ void zero_heads() {
    int i = threadIdx.x;
    if (i < HH) { g_max[i] = -3.4e38f; g_sum[i] = 0.0f; }
}

// ---------------- per-node precompute ----------------------------------------
// T = nf @ W_node ; P = nf[:, :64] @ aW1[0:64] ; Q = nf[:, :64] @ aW1[64:128]
__global__ void __launch_bounds__(NTP, 1)
prep_kernel(const float* __restrict__ nf, const float* __restrict__ W_node,
            const float* __restrict__ aW1) {
    extern __shared__ float sm[];
    float* nfT = sm;                  // [128][ASTP]
    float* Ws  = sm + 128 * ASTP;     // [NBUF][KC][128]
    const int tid = threadIdx.x;
    const long n0 = (long)blockIdx.x * 64;
    int nv = (int)(NN - n0); if (nv > 64) nv = 64;

    int pb = 0;
    prefetch_chunk<NTP>(W_node, KC, Ws, tid);

    for (int i = tid; i < 64 * 128; i += NTP) {
        int r = i >> 7, d = i & 127;
        nfT[d * ASTP + SWR(d, r)] = (r < nv) ? nf[(size_t)(n0 + r) * 128 + d] : 0.0f;
    }

    unsigned long long acc[4][4];
    gemm_stage<NTP, ASTP>(W_node, 128, nfT, Ws, acc, tid, true, pb, aW1, 64);
    store_global(acc, g_T, n0, nv, tid);
    gemm_stage<NTP, ASTP>(aW1, 64, nfT, Ws, acc, tid, true, pb, aW1 + 64 * 128, 64);
    store_global(acc, g_P, n0, nv, tid);
    gemm_stage<NTP, ASTP>(aW1 + 64 * 128, 64, nfT, Ws, acc, tid, true, pb, nullptr, 0);
    store_global(acc, g_Q, n0, nv, tid);
}

// ---------------- per-edge fused pipeline -------------------------------------
__global__ void __launch_bounds__(NTE, 1)
edge_kernel(const float* __restrict__ ea,   const float* __restrict__ esh,
            const float* __restrict__ fc1,  const float* __restrict__ b1,
            const float* __restrict__ fc2,  const float* __restrict__ b2,
            const float* __restrict__ fc3,  const float* __restrict__ b3,
            const float* __restrict__ W_sh, const float* __restrict__ aW1,
            const float* __restrict__ ab1,  const float* __restrict__ aW2,
            const float* __restrict__ ab2,  const float* __restrict__ aW3,
            const float* __restrict__ ab3,  const int* __restrict__ srcI,
            const int* __restrict__ dstI) {
    extern __shared__ float sm[];
    float* eaT  = sm;                    // [32][ASTE]
    float* eshT = eaT  + 32 * ASTE;      // [16][ASTE]
    float* hS   = eshT + 16 * ASTE;      // [128][ASTE]  (single, reused)
    float* Ws   = hS   + 128 * ASTE;     // [NBUF][KC][128]
    int*   sIdx = (int*)(Ws + NBUF * KC * 128);   // [128]
    int*   dIdx = sIdx + TILE_E;                  // [128]

    const int tid = threadIdx.x;
    const long e0 = (long)blockIdx.x * TILE_E;
    const int colg = tid & 31;
    const int rowb = (tid >> 5) * 8;
    const float* aW1c = aW1 + 128 * 128;   // edge-attr slice of aW1 (K=32)

    int pb = 0;
    prefetch_chunk<NTE>(fc1, 32, Ws, tid);

    if (tid < TILE_E)                sIdx[tid]          = srcI[e0 + tid];
    else if (tid < 2 * TILE_E)       dIdx[tid - TILE_E] = dstI[e0 + tid - TILE_E];

    for (int i = tid; i < TILE_E * 32; i += NTE) {
        int e = i >> 5, c = i & 31;
        eaT[c * ASTE + SWR(c, e)] = ea[(size_t)(e0 + e) * 32 + c];
    }
    for (int i = tid; i < TILE_E * 16; i += NTE) {
        int e = i >> 4, c = i & 15;
        eshT[c * ASTE + SWR(c, e)] = esh[(size_t)(e0 + e) * 16 + c];
    }

    unsigned long long acc[4][4];

    // ---- radial MLP: ea -> fc1 -> fc2 -> fc3 = scale (regs) ----
    gemm_stage<NTE, ASTE>(fc1, 32, eaT, Ws, acc, tid, true, pb, fc2, 128);
    store_act<ASTE>(acc, hS, b1, tid);                 // h := silu(fc1)
    gemm_stage<NTE, ASTE>(fc2, 128, hS, Ws, acc, tid, true, pb, fc3, 128);
    __syncthreads();                                   // h reread below
    store_act<ASTE>(acc, hS, b2, tid);                 // h := silu(fc2)
    gemm_stage<NTE, ASTE>(fc3, 128, hS, Ws, acc, tid, true, pb, W_sh, 16);

    float2 scale[4][4];
    {
        float4 b4 = *(const float4*)(b3 + colg * 4);
        float bb[4] = {b4.x, b4.y, b4.z, b4.w};
#pragma unroll
        for (int rp = 0; rp < 4; rp++)
#pragma unroll
            for (int c = 0; c < 4; c++) {
                float2 v = unpack2(acc[rp][c]);
                scale[rp][c].x = v.x + bb[c];
                scale[rp][c].y = v.y + bb[c];
            }
    }

    // ---- msg = silu(T[src]*scale + sh @ W_sh) ----
    gemm_stage<NTE, ASTE>(W_sh, 16, eshT, Ws, acc, tid, true, pb, aW1c, 32);
#pragma unroll
    for (int rp = 0; rp < 4; rp++) {
        int r0 = rowb + 2 * rp;
        float4 t0 = *(const float4*)(g_T + (size_t)sIdx[r0] * 128 + colg * 4);
        float4 t1 = *(const float4*)(g_T + (size_t)sIdx[r0 + 1] * 128 + colg * 4);
        float tA[4] = {t0.x, t0.y, t0.z, t0.w};
        float tB[4] = {t1.x, t1.y, t1.z, t1.w};
        float o0[4], o1[4];
#pragma unroll
        for (int c = 0; c < 4; c++) {
            float2 s = unpack2(acc[rp][c]);
            o0[c] = silu_f(tA[c] * scale[rp][c].x + s.x);
            o1[c] = silu_f(tB[c] * scale[rp][c].y + s.y);
        }
        *(float4*)(g_msg + (size_t)(e0 + r0) * 128 + colg * 4) =
            make_float4(o0[0], o0[1], o0[2], o0[3]);
        *(float4*)(g_msg + (size_t)(e0 + r0 + 1) * 128 + colg * 4) =
            make_float4(o1[0], o1[1], o1[2], o1[3]);
    }

    // ---- attention: acc = P[src] + Q[dst]; += ea @ aW1c; silu -> h ----
#pragma unroll
    for (int rp = 0; rp < 4; rp++) {
        int r0 = rowb + 2 * rp;
        float4 p0 = *(const float4*)(g_P + (size_t)sIdx[r0] * 128 + colg * 4);
        float4 q0 = *(const float4*)(g_Q + (size_t)dIdx[r0] * 128 + colg * 4);
        float4 p1 = *(const float4*)(g_P + (size_t)sIdx[r0 + 1] * 128 + colg * 4);
        float4 q1 = *(const float4*)(g_Q + (size_t)dIdx[r0 + 1] * 128 + colg * 4);
        acc[rp][0] = pack2(p0.x + q0.x, p1.x + q1.x);
        acc[rp][1] = pack2(p0.y + q0.y, p1.y + q1.y);
        acc[rp][2] = pack2(p0.z + q0.z, p1.z + q1.z);
        acc[rp][3] = pack2(p0.w + q0.w, p1.w + q1.w);
    }
    gemm_stage<NTE, ASTE>(aW1c, 32, eaT, Ws, acc, tid, false, pb, aW2, 128);
    store_act<ASTE>(acc, hS, ab1, tid);                // h := silu(alpha1)
    gemm_stage<NTE, ASTE>(aW2, 128, hS, Ws, acc, tid, true, pb, aW3, 8);
    __syncthreads();                                   // h reread below
    store_act<ASTE>(acc, hS, ab2, tid);                // h := silu(alpha2)

    // ---- aW3: [128 edges][128] @ [128][8]  (weights in ring slot pb) ----
    CP_WAIT(0);
    __syncthreads();
    {
        const float* W3 = Ws + pb * (KC * 128);
        int e  = tid & (TILE_E - 1);
        int ph = tid >> 7;        // 0..3 -> heads {2ph, 2ph+1}
        float a0 = 0.0f, a1 = 0.0f;
        for (int kg = 0; kg < 128; kg += 4) {
            const int es = e ^ SWX(kg);
            const float* hk = hS + kg * ASTE + es;
            const float* wk = W3 + kg * 8 + ph * 2;
#pragma unroll
            for (int k4 = 0; k4 < 4; k4++) {
                float av = hk[k4 * ASTE];
                a0 += av * wk[k4 * 8];
                a1 += av * wk[k4 * 8 + 1];
            }
        }
        g_a[(size_t)(e0 + e) * 8 + ph * 2]     = a0 + ab3[ph * 2];
        g_a[(size_t)(e0 + e) * 8 + ph * 2 + 1] = a1 + ab3[ph * 2 + 1];
    }
}

// ---------------- softmax reductions -----------------------------------------
__global__ void max_kernel() {
    __shared__ float smem[256];
    int tid = threadIdx.x;
    float mx = -3.4e38f;
    long stride = (long)gridDim.x * 256;
    for (long i = (long)blockIdx.x * 256 + tid; i < (long)EE * HH; i += stride)
        mx = fmaxf(mx, g_a[i]);
    smem[tid] = mx; __syncthreads();
    for (int s = 128; s >= 8; s >>= 1) {
        if (tid < s) smem[tid] = fmaxf(smem[tid], smem[tid + s]);
        __syncthreads();
    }
    if (tid < 8) atomicMaxFloat(&g_max[tid], smem[tid]);
}
__global__ void sum_kernel() {
    __shared__ float smem[256];
    int tid = threadIdx.x;
    int h = tid & 7;
    float mx = g_max[h];
    float s = 0.0f;
    long stride = (long)gridDim.x * 256;
    for (long i = (long)blockIdx.x * 256 + tid; i < (long)EE * HH; i += stride)
        s += __expf(g_a[i] - mx);
    smem[tid] = s; __syncthreads();
    for (int t = 128; t >= 8; t >>= 1) {
        if (tid < t) smem[tid] += smem[tid + t];
        __syncthreads();
    }
    if (tid < 8) atomicAdd(&g_sum[tid], smem[tid]);
}
__global__ void alpha_kernel() {
    __shared__ float smx[8], sinv[8];
    int tid = threadIdx.x;
    if (tid < 8) { smx[tid] = g_max[tid]; sinv[tid] = 1.0f / g_sum[tid]; }
    __syncthreads();
    int e = blockIdx.x * 256 + tid;
    if (e >= EE) return;
    float4 a0 = *(const float4*)(g_a + (size_t)e * 8);
    float4 a1 = *(const float4*)(g_a + (size_t)e * 8 + 4);
    float p = __expf(a0.x - smx[0]) * sinv[0] + __expf(a0.y - smx[1]) * sinv[1]
            + __expf(a0.z - smx[2]) * sinv[2] + __expf(a0.w - smx[3]) * sinv[3]
            + __expf(a1.x - smx[4]) * sinv[4] + __expf(a1.y - smx[5]) * sinv[5]
            + __expf(a1.z - smx[6]) * sinv[6] + __expf(a1.w - smx[7]) * sinv[7];
    g_alpha[e] = p * 0.125f;
}

// ---------------- weighted scatter-add (vectorized red) ------------------------
__global__ void scatter_kernel(const int* __restrict__ dstI) {
    size_t i = (size_t)blockIdx.x * 256 + threadIdx.x;
    if (i >= (size_t)EE * 32) return;
    int e = (int)(i >> 5);
    int q = (int)(i & 31);
    float am = g_alpha[e];
    float4 v = *(const float4*)(g_msg + (size_t)e * 128 + q * 4);
    float* base = g_agg + (size_t)dstI[e] * 128 + q * 4;
    asm volatile("red.global.add.v4.f32 [%0], {%1, %2, %3, %4};"
                 :: "l"(base), "f"(v.x * am), "f"(v.y * am),
                    "f"(v.z * am), "f"(v.w * am) : "memory");
}

// ---------------- out = LN(nf + agg @ W_out) -----------------------------------
__global__ void __launch_bounds__(NTP, 1)
node_kernel(const float* __restrict__ nf, const float* __restrict__ W_out,
            float* __restrict__ out) {
    extern __shared__ float sm[];
    float* aggT = sm;                  // [128][ASTP]
    float* Ws   = sm + 128 * ASTP;     // [NBUF][KC][128]
    const int tid = threadIdx.x;
    const int n0 = blockIdx.x * 64;
    int nv = NN - n0; if (nv > 64) nv = 64;

    int pb = 0;
    prefetch_chunk<NTP>(W_out, KC, Ws, tid);

    for (int i = tid; i < 64 * 128; i += NTP) {
        int r = i >> 7, d = i & 127;
        aggT[d * ASTP + SWR(d, r)] = (r < nv) ? g_agg[(size_t)(n0 + r) * 128 + d] : 0.0f;
    }

    unsigned long long acc[4][4];
    gemm_stage<NTP, ASTP>(W_out, 128, aggT, Ws, acc, tid, true, pb, nullptr, 0);

    const int colg = tid & 31;
    const int rowb = (tid >> 5) * 8;
#pragma unroll
    for (int rp = 0; rp < 4; rp++) {
        float2 v[4];
#pragma unroll
        for (int c = 0; c < 4; c++) v[c] = unpack2(acc[rp][c]);
#pragma unroll
        for (int half = 0; half < 2; half++) {
            int r = rowb + 2 * rp + half;
            int n = n0 + r;
            float4 x = make_float4(0.f, 0.f, 0.f, 0.f);
            if (r < nv) x = *(const float4*)(nf + (size_t)n * 128 + colg * 4);
            float y0 = x.x + (half ? v[0].y : v[0].x);
            float y1 = x.y + (half ? v[1].y : v[1].x);
            float y2 = x.z + (half ? v[2].y : v[2].x);
            float y3 = x.w + (half ? v[3].y : v[3].x);
            float s  = y0 + y1 + y2 + y3;
            float s2 = y0 * y0 + y1 * y1 + y2 * y2 + y3 * y3;
#pragma unroll
            for (int o = 16; o; o >>= 1) {
                s  += __shfl_xor_sync(0xffffffffu, s, o);
                s2 += __shfl_xor_sync(0xffffffffu, s2, o);
            }
            float mu  = s * (1.0f / 128.0f);
            float var = s2 * (1.0f / 128.0f) - mu * mu;
            float inv = rsqrtf(var + 1e-5f);
            if (r < nv) {
                *(float4*)(out + (size_t)n * 128 + colg * 4) =
                    make_float4((y0 - mu) * inv, (y1 - mu) * inv,
                                (y2 - mu) * inv, (y3 - mu) * inv);
            }
        }
    }
}

// ---------------- launch -----------------------------------------------------
extern "C" void kernel_launch(void* const* d_in, const int* in_sizes, int n_in,
                              void* d_out, int out_size) {
    const float* nf     = (const float*)d_in[0];
    const float* ea     = (const float*)d_in[1];
    const float* esh    = (const float*)d_in[2];
    const float* W_node = (const float*)d_in[3];
    const float* fc1    = (const float*)d_in[4];
    const float* b1     = (const float*)d_in[5];
    const float* fc2    = (const float*)d_in[6];
    const float* b2     = (const float*)d_in[7];
    const float* fc3    = (const float*)d_in[8];
    const float* b3     = (const float*)d_in[9];
    const float* W_sh   = (const float*)d_in[10];
    const float* aW1    = (const float*)d_in[11];
    const float* ab1    = (const float*)d_in[12];
    const float* aW2    = (const float*)d_in[13];
    const float* ab2    = (const float*)d_in[14];
    const float* aW3    = (const float*)d_in[15];
    const float* ab3    = (const float*)d_in[16];
    const float* W_out  = (const float*)d_in[17];
    const int*   eidx   = (const int*)d_in[18];
    const int*   srcI   = eidx;
    const int*   dstI   = eidx + EE;
    float* out = (float*)d_out;

    const int SMEM_PREP = (128 * ASTP + NBUF * KC * 128) * 4;
    const int SMEM_EDGE = ((32 + 16 + 128) * ASTE + NBUF * KC * 128) * 4
                          + 2 * TILE_E * (int)sizeof(int);
    const int SMEM_NODE = (128 * ASTP + NBUF * KC * 128) * 4;
    cudaFuncSetAttribute(prep_kernel, cudaFuncAttributeMaxDynamicSharedMemorySize, SMEM_PREP);
    cudaFuncSetAttribute(edge_kernel, cudaFuncAttributeMaxDynamicSharedMemorySize, SMEM_EDGE);
    cudaFuncSetAttribute(node_kernel, cudaFuncAttributeMaxDynamicSharedMemorySize, SMEM_NODE);

    zero_agg<<<(NN * DD + 255) / 256, 256>>>();
    zero_heads<<<1, 32>>>();
    prep_kernel<<<(NN + 63) / 64, NTP, SMEM_PREP>>>(nf, W_node, aW1);
    edge_kernel<<<EE / TILE_E, NTE, SMEM_EDGE>>>(ea, esh,
                                                 fc1, b1, fc2, b2, fc3, b3,
                                                 W_sh, aW1, ab1, aW2, ab2,
                                                 aW3, ab3, srcI, dstI);
    max_kernel<<<512, 256>>>();
    sum_kernel<<<512, 256>>>();
    alpha_kernel<<<(EE + 255) / 256, 256>>>();
    scatter_kernel<<<(int)(((size_t)EE * 32 + 255) / 256), 256>>>(dstI);
    node_kernel<<<(NN + 63) / 64, NTP, SMEM_NODE>>>(nf, W_out, out);
}